// round 3
// baseline (speedup 1.0000x reference)
#include <cuda_runtime.h>
#include <math.h>

#define N_CAPS 64
#define IN_CAPS 4096
#define CAP_DIM 32
#define IN_DIM 16
#define NUM_ROUTINGS 3
#define EPS 1e-7f
#define CHUNKS 16
#define CHUNK_I (IN_CAPS / CHUNKS)       // 256 inputs per scan block (1/thread)
#define SCAN_BLOCKS (N_CAPS * CHUNKS)    // 1024

// Scratch (__device__ globals: allocation-free rule)
__device__ float g_u[(size_t)N_CAPS * IN_CAPS * CAP_DIM];     // 33.5 MB
__device__ float g_vcum[N_CAPS * CAP_DIM];                    // sum of v over past iters
__device__ float g_pz[N_CAPS * CHUNKS];                       // partial sum-exp
__device__ float g_ps[N_CAPS * CHUNKS * CAP_DIM];             // partial weighted-u sums
__device__ unsigned int g_done[NUM_ROUTINGS] = {0, 0, 0};     // last-block counters

// ---------------------------------------------------------------------------
__global__ void zero_kernel() {
    int idx = blockIdx.x * blockDim.x + threadIdx.x;
    if (idx < N_CAPS * CAP_DIM) g_vcum[idx] = 0.0f;
    if (idx < NUM_ROUTINGS) g_done[idx] = 0u;
}

// ---------------------------------------------------------------------------
// u[n,i,d] = sum_k W[n,i,d,k] * x[i,k]
// One warp per (n,i); lane = d. Warp covers a contiguous 2KB of W. HBM-bound.
// ---------------------------------------------------------------------------
__global__ __launch_bounds__(256) void uhat_kernel(const float* __restrict__ W,
                                                   const float* __restrict__ x) {
    int w = blockIdx.x * (blockDim.x >> 5) + (threadIdx.x >> 5);
    int lane = threadIdx.x & 31;
    int i = w & (IN_CAPS - 1);

    const float4* xp = reinterpret_cast<const float4*>(x + (size_t)i * IN_DIM);
    float4 x0 = xp[0], x1 = xp[1], x2 = xp[2], x3 = xp[3];

    const float4* wp = reinterpret_cast<const float4*>(
        W + (((size_t)w * CAP_DIM) + lane) * IN_DIM);
    float4 w0 = wp[0], w1 = wp[1], w2 = wp[2], w3 = wp[3];

    float acc = w0.x * x0.x + w0.y * x0.y + w0.z * x0.z + w0.w * x0.w;
    acc      += w1.x * x1.x + w1.y * x1.y + w1.z * x1.z + w1.w * x1.w;
    acc      += w2.x * x2.x + w2.y * x2.y + w2.z * x2.z + w2.w * x2.w;
    acc      += w3.x * x3.x + w3.y * x3.y + w3.z * x3.z + w3.w * x3.w;

    g_u[(size_t)w * CAP_DIM + lane] = acc;
}

// ---------------------------------------------------------------------------
// Routing scan, one pass over u per iteration, combine fused as last-block tail.
// Block = (chunk, n), 256 threads, 1 input-capsule per thread.
//   l_i = u_i . V_cum ;  e_i = exp(l_i)        (softmax is shift-invariant;
//                                               logits bounded -> no max needed)
//   partials: Z = sum e, S[d] = sum e*u_i[d]
// Last finishing block merges partials, squashes, updates V_cum, writes out.
// ---------------------------------------------------------------------------
__global__ __launch_bounds__(256) void scan_kernel(int iter, float* __restrict__ out) {
    const int n = blockIdx.y;
    const int chunk = blockIdx.x;
    const int tid = threadIdx.x;
    const int wid = tid >> 5;
    const int lane = tid & 31;

    __shared__ float sm_v[CAP_DIM];
    __shared__ float sm_wred[8];
    __shared__ float sm_wvec[8][CAP_DIM];

    if (tid < CAP_DIM) sm_v[tid] = g_vcum[n * CAP_DIM + tid];
    __syncthreads();

    const int i = chunk * CHUNK_I + tid;
    const float4* up = reinterpret_cast<const float4*>(
        g_u + ((size_t)n * IN_CAPS + i) * CAP_DIM);

    float4 U[8];
#pragma unroll
    for (int j = 0; j < 8; j++) U[j] = up[j];

    float l = 0.0f;
#pragma unroll
    for (int j = 0; j < 8; j++) {
        l += U[j].x * sm_v[4 * j + 0] + U[j].y * sm_v[4 * j + 1]
           + U[j].z * sm_v[4 * j + 2] + U[j].w * sm_v[4 * j + 3];
    }
    const float e = __expf(l);

#pragma unroll
    for (int j = 0; j < 8; j++) {
        U[j].x *= e; U[j].y *= e; U[j].z *= e; U[j].w *= e;
    }

    // warp reduce Z and the 32-dim vector
    float z = e;
#pragma unroll
    for (int o = 16; o > 0; o >>= 1) z += __shfl_xor_sync(0xffffffffu, z, o);
#pragma unroll
    for (int j = 0; j < 8; j++) {
#pragma unroll
        for (int o = 16; o > 0; o >>= 1) {
            U[j].x += __shfl_xor_sync(0xffffffffu, U[j].x, o);
            U[j].y += __shfl_xor_sync(0xffffffffu, U[j].y, o);
            U[j].z += __shfl_xor_sync(0xffffffffu, U[j].z, o);
            U[j].w += __shfl_xor_sync(0xffffffffu, U[j].w, o);
        }
    }
    if (lane == 0) {
        sm_wred[wid] = z;
#pragma unroll
        for (int j = 0; j < 8; j++) {
            sm_wvec[wid][4 * j + 0] = U[j].x;
            sm_wvec[wid][4 * j + 1] = U[j].y;
            sm_wvec[wid][4 * j + 2] = U[j].z;
            sm_wvec[wid][4 * j + 3] = U[j].w;
        }
    }
    __syncthreads();

    const int slot = n * CHUNKS + chunk;
    if (tid == 0) {
        float zt = 0.0f;
#pragma unroll
        for (int k = 0; k < 8; k++) zt += sm_wred[k];
        g_pz[slot] = zt;
    }
    if (tid < CAP_DIM) {
        float s = 0.0f;
#pragma unroll
        for (int k = 0; k < 8; k++) s += sm_wvec[k][tid];
        g_ps[slot * CAP_DIM + tid] = s;
    }

    // ---- last-block combine tail ----
    __shared__ unsigned int sm_last;
    __threadfence();
    __syncthreads();
    if (tid == 0) {
        unsigned int prev = atomicAdd(&g_done[iter], 1u);
        sm_last = (prev == SCAN_BLOCKS - 1) ? 1u : 0u;
    }
    __syncthreads();
    if (!sm_last) return;
    if (tid == 0) g_done[iter] = 0u;   // self-reset for next graph replay

    __shared__ float sm_invZ[N_CAPS];
    __shared__ float sm_s[N_CAPS * CAP_DIM];
    __shared__ float sm_red2[8];
    __shared__ float sm_scale;

    if (tid < N_CAPS) {
        float zt = 0.0f;
#pragma unroll
        for (int c = 0; c < CHUNKS; c++) zt += g_pz[tid * CHUNKS + c];
        sm_invZ[tid] = 1.0f / zt;
    }
    __syncthreads();

    float sq = 0.0f;
#pragma unroll
    for (int r = 0; r < 8; r++) {
        int idx = tid + r * 256;            // idx = n*32 + d
        int n2 = idx >> 5;
        int d = idx & 31;
        float s = 0.0f;
#pragma unroll
        for (int c = 0; c < CHUNKS; c++)
            s += g_ps[(n2 * CHUNKS + c) * CAP_DIM + d];
        s *= sm_invZ[n2];
        sm_s[idx] = s;
        sq += s * s;
    }
#pragma unroll
    for (int o = 16; o > 0; o >>= 1) sq += __shfl_xor_sync(0xffffffffu, sq, o);
    if (lane == 0) sm_red2[wid] = sq;
    __syncthreads();
    if (tid == 0) {
        float t = 0.0f;
#pragma unroll
        for (int k = 0; k < 8; k++) t += sm_red2[k];
        sm_scale = t / (1.0f + t) / (sqrtf(t) + EPS);
    }
    __syncthreads();
    const float scale = sm_scale;

#pragma unroll
    for (int r = 0; r < 8; r++) {
        int idx = tid + r * 256;
        float v = sm_s[idx] * scale;
        g_vcum[idx] += v;
        if (out) out[idx] = v;
    }
}

// ---------------------------------------------------------------------------
extern "C" void kernel_launch(void* const* d_in, const int* in_sizes, int n_in,
                              void* d_out, int out_size) {
    const float* x = (const float*)d_in[0];
    const float* W = (const float*)d_in[1];
    if (in_sizes[0] > in_sizes[1]) { const float* t = x; x = W; W = t; }
    float* out = (float*)d_out;

    zero_kernel<<<8, 256>>>();

    const int pairs = N_CAPS * IN_CAPS;
    uhat_kernel<<<pairs / 8, 256>>>(W, x);

    dim3 scan_grid(CHUNKS, N_CAPS);
    for (int t = 0; t < NUM_ROUTINGS; t++) {
        scan_kernel<<<scan_grid, 256>>>(t, t == NUM_ROUTINGS - 1 ? out : nullptr);
    }
}

// round 4
// speedup vs baseline: 1.0817x; 1.0817x over previous
#include <cuda_runtime.h>
#include <math.h>

#define N_CAPS 64
#define IN_CAPS 4096
#define CAP_DIM 32
#define IN_DIM 16
#define NUM_ROUTINGS 3
#define EPS 1e-7f
#define CHUNKS 16
#define CHUNK_I (IN_CAPS / CHUNKS)       // 256 inputs per scan block (1/thread)
#define SCAN_BLOCKS (N_CAPS * CHUNKS)    // 1024

// Scratch (__device__ globals: allocation-free rule)
__device__ float g_u[(size_t)N_CAPS * IN_CAPS * CAP_DIM];     // 33.5 MB
__device__ float g_vcum[N_CAPS * CAP_DIM];                    // sum of v over past iters
__device__ float g_pz[N_CAPS * CHUNKS];                       // partial sum-exp
__device__ float g_ps[N_CAPS * CHUNKS * CAP_DIM];             // partial weighted-u sums
__device__ unsigned int g_done[NUM_ROUTINGS] = {0u, 0u, 0u};  // last-block counters

// ---------------------------------------------------------------------------
// u[n,i,d] = sum_k W[n,i,d,k] * x[i,k]
// One warp per (n,i); lane = d. Warp covers a contiguous 2KB of W. HBM-bound,
// measured ~7.9 TB/s effective — at the roofline.
// ---------------------------------------------------------------------------
__global__ __launch_bounds__(256) void uhat_kernel(const float* __restrict__ W,
                                                   const float* __restrict__ x) {
    int w = blockIdx.x * (blockDim.x >> 5) + (threadIdx.x >> 5);
    int lane = threadIdx.x & 31;
    int i = w & (IN_CAPS - 1);

    const float4* xp = reinterpret_cast<const float4*>(x + (size_t)i * IN_DIM);
    float4 x0 = xp[0], x1 = xp[1], x2 = xp[2], x3 = xp[3];

    const float4* wp = reinterpret_cast<const float4*>(
        W + (((size_t)w * CAP_DIM) + lane) * IN_DIM);
    float4 w0 = wp[0], w1 = wp[1], w2 = wp[2], w3 = wp[3];

    float acc = w0.x * x0.x + w0.y * x0.y + w0.z * x0.z + w0.w * x0.w;
    acc      += w1.x * x1.x + w1.y * x1.y + w1.z * x1.z + w1.w * x1.w;
    acc      += w2.x * x2.x + w2.y * x2.y + w2.z * x2.z + w2.w * x2.w;
    acc      += w3.x * x3.x + w3.y * x3.y + w3.z * x3.z + w3.w * x3.w;

    g_u[(size_t)w * CAP_DIM + lane] = acc;
}

// ---------------------------------------------------------------------------
// Routing scan (one pass over u), combine fused as last-block tail.
// Block = (chunk, n), 256 threads, 1 input-capsule per thread.
//   iter==0: e = 1 (logits are 0)
//   else:    e = exp(u_i . V_cum)   (softmax shift-invariance: logits bounded)
// Warp reduce of the 32-dim S vector via exchange-halving: 31 shfls total,
// lane l ends holding S[d=l].
// ---------------------------------------------------------------------------
__global__ __launch_bounds__(256) void scan_kernel(int iter, float* __restrict__ out) {
    const int n = blockIdx.y;
    const int chunk = blockIdx.x;
    const int tid = threadIdx.x;
    const int wid = tid >> 5;
    const int lane = tid & 31;

    __shared__ float sm_v[CAP_DIM];
    __shared__ float sm_wred[8];
    __shared__ float sm_wvec[8][CAP_DIM];

    if (iter != 0) {
        if (tid < CAP_DIM) sm_v[tid] = g_vcum[n * CAP_DIM + tid];
        __syncthreads();
    }

    const int i = chunk * CHUNK_I + tid;
    const float4* up = reinterpret_cast<const float4*>(
        g_u + ((size_t)n * IN_CAPS + i) * CAP_DIM);

    float A[CAP_DIM];   // becomes e * u_i, then exchange-halving workspace
    {
        float4 U[8];
#pragma unroll
        for (int j = 0; j < 8; j++) U[j] = up[j];

        float e;
        if (iter == 0) {
            e = 1.0f;
        } else {
            float l = 0.0f;
#pragma unroll
            for (int j = 0; j < 8; j++) {
                l += U[j].x * sm_v[4 * j + 0] + U[j].y * sm_v[4 * j + 1]
                   + U[j].z * sm_v[4 * j + 2] + U[j].w * sm_v[4 * j + 3];
            }
            e = __expf(l);
        }

#pragma unroll
        for (int j = 0; j < 8; j++) {
            A[4 * j + 0] = e * U[j].x;
            A[4 * j + 1] = e * U[j].y;
            A[4 * j + 2] = e * U[j].z;
            A[4 * j + 3] = e * U[j].w;
        }

        // warp sum of e (Z partial)
        float z = e;
#pragma unroll
        for (int o = 16; o > 0; o >>= 1) z += __shfl_xor_sync(0xffffffffu, z, o);
        if (lane == 0) sm_wred[wid] = z;
    }

    // Exchange-halving vector reduce: after 5 steps A[0] = sum over warp of
    // element d == lane. 31 shfls total.
#pragma unroll
    for (int m = 16; m >= 1; m >>= 1) {
        const bool hi = (lane & m) != 0;
#pragma unroll
        for (int t = 0; t < m; t++) {
            float send = hi ? A[t] : A[t + m];
            float recv = __shfl_xor_sync(0xffffffffu, send, m);
            A[t] = (hi ? A[t + m] : A[t]) + recv;
        }
    }
    sm_wvec[wid][lane] = A[0];
    __syncthreads();

    const int slot = n * CHUNKS + chunk;
    if (tid < CAP_DIM) {
        float s = 0.0f;
#pragma unroll
        for (int k = 0; k < 8; k++) s += sm_wvec[k][tid];
        g_ps[slot * CAP_DIM + tid] = s;
    }
    if (tid == 0) {
        float zt = 0.0f;
#pragma unroll
        for (int k = 0; k < 8; k++) zt += sm_wred[k];
        g_pz[slot] = zt;
    }

    // ---- last-block combine tail ----
    __shared__ unsigned int sm_last;
    __threadfence();
    __syncthreads();
    if (tid == 0) {
        unsigned int prev = atomicAdd(&g_done[iter], 1u);
        sm_last = (prev == SCAN_BLOCKS - 1) ? 1u : 0u;
    }
    __syncthreads();
    if (!sm_last) return;
    if (tid == 0) g_done[iter] = 0u;   // self-reset for next graph replay
    __threadfence();

    __shared__ float sm_invZ[N_CAPS];
    __shared__ float sm_s[N_CAPS * CAP_DIM];
    __shared__ float sm_red2[8];
    __shared__ float sm_scale;

    if (tid < N_CAPS) {
        float zt = 0.0f;
#pragma unroll
        for (int c = 0; c < CHUNKS; c++) zt += g_pz[tid * CHUNKS + c];
        sm_invZ[tid] = 1.0f / zt;
    }
    __syncthreads();

    float sq = 0.0f;
#pragma unroll
    for (int r = 0; r < 8; r++) {
        int idx = tid + r * 256;            // idx = n*32 + d
        int n2 = idx >> 5;
        int d = idx & 31;
        float s = 0.0f;
#pragma unroll
        for (int c = 0; c < CHUNKS; c++)
            s += g_ps[(n2 * CHUNKS + c) * CAP_DIM + d];
        s *= sm_invZ[n2];
        sm_s[idx] = s;
        sq += s * s;
    }
#pragma unroll
    for (int o = 16; o > 0; o >>= 1) sq += __shfl_xor_sync(0xffffffffu, sq, o);
    if (lane == 0) sm_red2[wid] = sq;
    __syncthreads();
    if (tid == 0) {
        float t = 0.0f;
#pragma unroll
        for (int k = 0; k < 8; k++) t += sm_red2[k];
        sm_scale = t / (1.0f + t) / (sqrtf(t) + EPS);
    }
    __syncthreads();
    const float scale = sm_scale;

    const bool last_iter = (iter == NUM_ROUTINGS - 1);
#pragma unroll
    for (int r = 0; r < 8; r++) {
        int idx = tid + r * 256;
        float v = sm_s[idx] * scale;
        if (last_iter) {
            out[idx] = v;
        } else if (iter == 0) {
            g_vcum[idx] = v;            // overwrite: no zero-init launch needed
        } else {
            g_vcum[idx] += v;
        }
    }
}

// ---------------------------------------------------------------------------
extern "C" void kernel_launch(void* const* d_in, const int* in_sizes, int n_in,
                              void* d_out, int out_size) {
    const float* x = (const float*)d_in[0];
    const float* W = (const float*)d_in[1];
    if (in_sizes[0] > in_sizes[1]) { const float* t = x; x = W; W = t; }
    float* out = (float*)d_out;

    const int pairs = N_CAPS * IN_CAPS;
    uhat_kernel<<<pairs / 8, 256>>>(W, x);

    dim3 scan_grid(CHUNKS, N_CAPS);
    for (int t = 0; t < NUM_ROUTINGS; t++) {
        scan_kernel<<<scan_grid, 256>>>(t, t == NUM_ROUTINGS - 1 ? out : nullptr);
    }
}

// round 6
// speedup vs baseline: 1.3225x; 1.2226x over previous
#include <cuda_runtime.h>
#include <cuda_fp16.h>
#include <math.h>

#define N_CAPS 64
#define IN_CAPS 4096
#define CAP_DIM 32
#define IN_DIM 16
#define EPS 1e-7f

#define GRID 128                 // <= 148 SMs: all blocks co-resident (1/SM, smem-bound)
#define TPB 512
#define NWARP 16
#define PPB (N_CAPS * IN_CAPS / GRID)   // 2048 pairs per block
#define PPW (PPB / NWARP)               // 128 pairs per warp
#define SMEM_U_BYTES (PPB * CAP_DIM * 2)  // 131072 B of fp16 u

// globals (allocation-free rule)
__device__ float g_ps[GRID][CAP_DIM];     // per-block partial S
__device__ float g_pz[GRID];              // per-block partial Z
__device__ float g_v[N_CAPS * CAP_DIM];   // cumulative v
__device__ unsigned int g_cnt[3] = {0u, 0u, 0u};
__device__ unsigned int g_flag[2] = {0u, 0u};

__global__ void __launch_bounds__(TPB, 1)
caps_kernel(const float* __restrict__ W, const float* __restrict__ x,
            float* __restrict__ out)
{
    extern __shared__ unsigned int u_sm[];   // half2 words: [pair*16 + k] holds dims 2k,2k+1
    const int tid  = threadIdx.x;
    const int wid  = tid >> 5;
    const int lane = tid & 31;
    const int blk  = blockIdx.x;
    const int n     = blk >> 1;                      // 2 blocks per output capsule
    const int ibase = (blk & 1) * (IN_CAPS / 2);

    __shared__ float2 sm_A[NWARP][CAP_DIM];
    __shared__ float  sm_z[NWARP];
    __shared__ float  sm_red[NWARP];
    __shared__ float  sm_scale;
    __shared__ unsigned int sm_last;

    // ---------------- Phase A: u = W.x (HBM-bound), iter-0 partial exact in fp32,
    // u stashed to SMEM as fp16 (11-bit mantissa: rel_err ~2e-4, under 1e-3 budget)
    {
        float A0 = 0.f;   // lane = dim d; sum of u over this warp's pairs
        const int p0 = wid * PPW;
        const float4* wp = reinterpret_cast<const float4*>(
            W + (((size_t)(n * IN_CAPS + ibase + p0)) * CAP_DIM + lane) * IN_DIM);
        float4 w0 = wp[0], w1 = wp[1], w2 = wp[2], w3 = wp[3];

        for (int p = 0; p < PPW; p++) {
            // prefetch next pair's W row (clamped on last iter; loads stay in-bounds)
            const float4* np = wp + ((p + 1 < PPW) ? (CAP_DIM * IN_DIM / 4) : 0);
            float4 m0 = np[0], m1 = np[1], m2 = np[2], m3 = np[3];

            const float4* xp = reinterpret_cast<const float4*>(
                x + (size_t)(ibase + p0 + p) * IN_DIM);
            float4 x0 = __ldg(xp), x1 = __ldg(xp + 1), x2 = __ldg(xp + 2), x3 = __ldg(xp + 3);

            float u = w0.x * x0.x + w0.y * x0.y + w0.z * x0.z + w0.w * x0.w
                    + w1.x * x1.x + w1.y * x1.y + w1.z * x1.z + w1.w * x1.w
                    + w2.x * x2.x + w2.y * x2.y + w2.z * x2.z + w2.w * x2.w
                    + w3.x * x3.x + w3.y * x3.y + w3.z * x3.z + w3.w * x3.w;
            A0 += u;

            // pack two dims per word: lanes 0..15 gather (u@2l, u@2l+1)
            float lo = __shfl_sync(0xffffffffu, u, (lane * 2) & 31);
            float hi = __shfl_sync(0xffffffffu, u, (lane * 2 + 1) & 31);
            if (lane < 16) {
                __half2 h = __floats2half2_rn(lo, hi);
                u_sm[(p0 + p) * 16 + lane] = *reinterpret_cast<unsigned int*>(&h);
            }
            w0 = m0; w1 = m1; w2 = m2; w3 = m3;
            wp += (CAP_DIM * IN_DIM / 4);
        }
        sm_A[wid][lane].x = A0;
    }
    __syncthreads();
    if (tid < CAP_DIM) {                    // block partial S (iter0: e == 1, exact fp32)
        float s = 0.f;
#pragma unroll
        for (int k = 0; k < NWARP; k++) s += sm_A[k][tid].x;
        g_ps[blk][tid] = s;
    }

    // ---------------- 3 routing iterations with software grid barrier
    for (int t = 0; t < 3; t++) {
        if (t > 0) {
            // Phase B: partials from SMEM u. lane k=lane&15 owns dims 2k,2k+1;
            // lanes 0-15 process even pair offsets, 16-31 odd offsets.
            const float2 vv = *reinterpret_cast<const float2*>(
                &g_v[n * CAP_DIM + 2 * (lane & 15)]);
            float ax = 0.f, ay = 0.f, z = 0.f;
            const int pbase = wid * PPW + ((lane >> 4) & 1);
#pragma unroll 4
            for (int s2 = 0; s2 < PPW / 2; s2++) {
                unsigned int wrd = u_sm[(pbase + 2 * s2) * 16 + (lane & 15)];
                __half2 h = *reinterpret_cast<__half2*>(&wrd);
                float2 uu = __half22float2(h);
                float dt = uu.x * vv.x + uu.y * vv.y;
                dt += __shfl_xor_sync(0xffffffffu, dt, 1);
                dt += __shfl_xor_sync(0xffffffffu, dt, 2);
                dt += __shfl_xor_sync(0xffffffffu, dt, 4);
                dt += __shfl_xor_sync(0xffffffffu, dt, 8);   // 16-lane group dot
                float e = __expf(dt);
                ax += e * uu.x; ay += e * uu.y; z += e;
            }
            sm_A[wid][lane] = make_float2(ax, ay);
#pragma unroll
            for (int o = 16; o > 0; o >>= 1) z += __shfl_xor_sync(0xffffffffu, z, o);
            if (lane == 0) sm_z[wid] = z;
            __syncthreads();
            if (tid < CAP_DIM) {
                const int k = tid >> 1, j = tid & 1;
                float s = 0.f;
#pragma unroll
                for (int w2 = 0; w2 < NWARP; w2++) {
                    float2 a = sm_A[w2][k];
                    float2 b2 = sm_A[w2][k + 16];
                    s += j ? (a.y + b2.y) : (a.x + b2.x);
                }
                g_ps[blk][tid] = s;
            } else if (tid == CAP_DIM) {
                float zt = 0.f;
#pragma unroll
                for (int w2 = 0; w2 < NWARP; w2++) zt += sm_z[w2];
                g_pz[blk] = zt * (1.f / 16.f);   // each pair's e counted 16x
            }
        }

        // ---- arrive ----
        __threadfence();
        __syncthreads();
        if (tid == 0) {
            unsigned int prev = atomicAdd(&g_cnt[t], 1u);
            sm_last = (prev == GRID - 1) ? 1u : 0u;
        }
        __syncthreads();

        if (sm_last) {
            // ---- combine (deterministic fixed-order reduction) ----
            __threadfence();
            float sr[4]; float sq = 0.f;
#pragma unroll
            for (int r = 0; r < 4; r++) {
                int idx = tid + r * TPB;        // idx = n2*32 + d  (2048 total)
                int n2 = idx >> 5, d = idx & 31;
                float num = g_ps[2 * n2][d] + g_ps[2 * n2 + 1][d];
                float Z = (t == 0) ? (float)IN_CAPS : (g_pz[2 * n2] + g_pz[2 * n2 + 1]);
                float s = num / Z;
                sr[r] = s; sq += s * s;
            }
#pragma unroll
            for (int o = 16; o > 0; o >>= 1) sq += __shfl_xor_sync(0xffffffffu, sq, o);
            if (lane == 0) sm_red[wid] = sq;
            __syncthreads();
            if (tid == 0) {
                float tt = 0.f;
#pragma unroll
                for (int k = 0; k < NWARP; k++) tt += sm_red[k];
                sm_scale = tt / (1.0f + tt) / (sqrtf(tt) + EPS);
            }
            __syncthreads();
            const float scale = sm_scale;
#pragma unroll
            for (int r = 0; r < 4; r++) {
                int idx = tid + r * TPB;
                float v = sr[r] * scale;
                if (t == 0)      g_v[idx] = v;       // overwrite: no init launch
                else if (t == 1) g_v[idx] += v;      // cumulative for iter 2
                else             out[idx] = v;       // final output
            }
            __threadfence();
            __syncthreads();
            if (tid == 0) {
                if (t < 2) {
                    atomicExch(&g_flag[t], 1u);      // release
                } else {
                    g_cnt[0] = 0u; g_cnt[1] = 0u; g_cnt[2] = 0u;   // replay reset
                    g_flag[0] = 0u; g_flag[1] = 0u;
                }
            }
        } else {
            if (t == 2) return;                      // partials written; done
            if (tid == 0) {
                while (atomicAdd(&g_flag[t], 0u) == 0u) __nanosleep(64);
            }
            __syncthreads();
            __threadfence();
        }
    }
}

// ---------------------------------------------------------------------------
extern "C" void kernel_launch(void* const* d_in, const int* in_sizes, int n_in,
                              void* d_out, int out_size) {
    const float* x = (const float*)d_in[0];
    const float* W = (const float*)d_in[1];
    if (in_sizes[0] > in_sizes[1]) { const float* t = x; x = W; W = t; }
    float* out = (float*)d_out;

    cudaFuncSetAttribute(caps_kernel,
                         cudaFuncAttributeMaxDynamicSharedMemorySize, SMEM_U_BYTES);
    caps_kernel<<<GRID, TPB, SMEM_U_BYTES>>>(W, x, out);
}

// round 7
// speedup vs baseline: 1.3420x; 1.0147x over previous
#include <cuda_runtime.h>
#include <cuda_fp16.h>
#include <math.h>

#define N_CAPS 64
#define IN_CAPS 4096
#define CAP_DIM 32
#define IN_DIM 16
#define EPS 1e-7f

#define GRID 128                 // <= 148 SMs: all blocks co-resident (1 block/SM)
#define TPB 1024
#define NWARP 32
#define PPB (N_CAPS * IN_CAPS / GRID)   // 2048 pairs per block
#define PPW (PPB / NWARP)               // 64 pairs per warp
#define SMEM_U_BYTES (PPB * CAP_DIM * 2)  // 131072 B of fp16 u

// globals (allocation-free rule)
__device__ float g_ps[GRID][CAP_DIM];     // per-block partial S
__device__ float g_pz[GRID];              // per-block partial Z
__device__ float g_v[N_CAPS * CAP_DIM];   // cumulative v
__device__ unsigned int g_cnt[3] = {0u, 0u, 0u};
__device__ unsigned int g_flag[2] = {0u, 0u};

__global__ void __launch_bounds__(TPB, 1)
caps_kernel(const float* __restrict__ W, const float* __restrict__ x,
            float* __restrict__ out)
{
    extern __shared__ unsigned int u_sm[];   // half2 words: [pair*16 + k] = dims 2k,2k+1
    __half* const u_h = reinterpret_cast<__half*>(u_sm);
    const int tid  = threadIdx.x;
    const int wid  = tid >> 5;
    const int lane = tid & 31;
    const int blk  = blockIdx.x;
    const int n     = blk >> 1;                      // 2 blocks per output capsule
    const int ibase = (blk & 1) * (IN_CAPS / 2);

    __shared__ float2 sm_A[NWARP][CAP_DIM];
    __shared__ float  sm_z[NWARP];
    __shared__ float  sm_red[NWARP];
    __shared__ float  sm_scale;
    __shared__ unsigned int sm_last;

    // ---------------- Phase A: u = W.x (HBM-bound). iter-0 partial exact in fp32.
    // Each lane owns dim d = lane; stores its u directly as fp16 (STS.U16) at
    // pair*64B + lane*2 — identical layout Phase B reads. No shuffles.
    {
        float A0 = 0.f;
        const int p0 = wid * PPW;
        const float4* wp = reinterpret_cast<const float4*>(
            W + (((size_t)(n * IN_CAPS + ibase + p0)) * CAP_DIM + lane) * IN_DIM);
        const float4* xp = reinterpret_cast<const float4*>(
            x + (size_t)(ibase + p0) * IN_DIM);
        const int WSTRIDE = CAP_DIM * IN_DIM / 4;    // float4s per pair

        for (int p = 0; p < PPW; p += 2) {
            // hoist both pairs' W loads: 8 LDG.128 in flight
            float4 a0 = wp[0], a1 = wp[1], a2 = wp[2], a3 = wp[3];
            float4 b0 = wp[WSTRIDE], b1 = wp[WSTRIDE + 1],
                   b2 = wp[WSTRIDE + 2], b3 = wp[WSTRIDE + 3];

            float4 x0 = __ldg(xp + 0), x1 = __ldg(xp + 1),
                   x2 = __ldg(xp + 2), x3 = __ldg(xp + 3);
            float ua = a0.x * x0.x + a0.y * x0.y + a0.z * x0.z + a0.w * x0.w
                     + a1.x * x1.x + a1.y * x1.y + a1.z * x1.z + a1.w * x1.w
                     + a2.x * x2.x + a2.y * x2.y + a2.z * x2.z + a2.w * x2.w
                     + a3.x * x3.x + a3.y * x3.y + a3.z * x3.z + a3.w * x3.w;
            A0 += ua;
            u_h[(p0 + p) * CAP_DIM + lane] = __float2half_rn(ua);

            float4 y0 = __ldg(xp + 4), y1 = __ldg(xp + 5),
                   y2 = __ldg(xp + 6), y3 = __ldg(xp + 7);
            float ub = b0.x * y0.x + b0.y * y0.y + b0.z * y0.z + b0.w * y0.w
                     + b1.x * y1.x + b1.y * y1.y + b1.z * y1.z + b1.w * y1.w
                     + b2.x * y2.x + b2.y * y2.y + b2.z * y2.z + b2.w * y2.w
                     + b3.x * y3.x + b3.y * y3.y + b3.z * y3.z + b3.w * y3.w;
            A0 += ub;
            u_h[(p0 + p + 1) * CAP_DIM + lane] = __float2half_rn(ub);

            wp += 2 * WSTRIDE;
            xp += 8;
        }
        sm_A[wid][lane].x = A0;
    }
    __syncthreads();
    if (tid < CAP_DIM) {                    // block partial S (iter0: e == 1, exact fp32)
        float s = 0.f;
#pragma unroll
        for (int k = 0; k < NWARP; k++) s += sm_A[k][tid].x;
        g_ps[blk][tid] = s;
    }

    // ---------------- 3 routing iterations with software grid barrier
    for (int t = 0; t < 3; t++) {
        if (t > 0) {
            // Phase B: partials from SMEM u. lane k=lane&15 owns dims 2k,2k+1;
            // lanes 0-15 process even pair offsets, 16-31 odd offsets.
            const float2 vv = *reinterpret_cast<const float2*>(
                &g_v[n * CAP_DIM + 2 * (lane & 15)]);
            float ax = 0.f, ay = 0.f, z = 0.f;
            const int pbase = wid * PPW + ((lane >> 4) & 1);
#pragma unroll 4
            for (int s2 = 0; s2 < PPW / 2; s2++) {
                unsigned int wrd = u_sm[(pbase + 2 * s2) * 16 + (lane & 15)];
                __half2 h = *reinterpret_cast<__half2*>(&wrd);
                float2 uu = __half22float2(h);
                float dt = uu.x * vv.x + uu.y * vv.y;
                dt += __shfl_xor_sync(0xffffffffu, dt, 1);
                dt += __shfl_xor_sync(0xffffffffu, dt, 2);
                dt += __shfl_xor_sync(0xffffffffu, dt, 4);
                dt += __shfl_xor_sync(0xffffffffu, dt, 8);   // 16-lane group dot
                float e = __expf(dt);
                ax += e * uu.x; ay += e * uu.y; z += e;
            }
            sm_A[wid][lane] = make_float2(ax, ay);
#pragma unroll
            for (int o = 16; o > 0; o >>= 1) z += __shfl_xor_sync(0xffffffffu, z, o);
            if (lane == 0) sm_z[wid] = z;
            __syncthreads();
            if (tid < CAP_DIM) {
                const int k = tid >> 1, j = tid & 1;
                float s = 0.f;
#pragma unroll
                for (int w2 = 0; w2 < NWARP; w2++) {
                    float2 a = sm_A[w2][k];
                    float2 b2 = sm_A[w2][k + 16];
                    s += j ? (a.y + b2.y) : (a.x + b2.x);
                }
                g_ps[blk][tid] = s;
            } else if (tid == CAP_DIM) {
                float zt = 0.f;
#pragma unroll
                for (int w2 = 0; w2 < NWARP; w2++) zt += sm_z[w2];
                g_pz[blk] = zt * (1.f / 16.f);   // each pair's e counted 16x
            }
        }

        // ---- arrive ----
        __threadfence();
        __syncthreads();
        if (tid == 0) {
            unsigned int prev = atomicAdd(&g_cnt[t], 1u);
            sm_last = (prev == GRID - 1) ? 1u : 0u;
        }
        __syncthreads();

        if (sm_last) {
            // ---- combine (deterministic fixed-order reduction) ----
            __threadfence();
            float sr[2]; float sq = 0.f;
#pragma unroll
            for (int r = 0; r < 2; r++) {
                int idx = tid + r * TPB;        // idx = n2*32 + d  (2048 total)
                int n2 = idx >> 5, d = idx & 31;
                float num = g_ps[2 * n2][d] + g_ps[2 * n2 + 1][d];
                float Z = (t == 0) ? (float)IN_CAPS : (g_pz[2 * n2] + g_pz[2 * n2 + 1]);
                float s = num / Z;
                sr[r] = s; sq += s * s;
            }
#pragma unroll
            for (int o = 16; o > 0; o >>= 1) sq += __shfl_xor_sync(0xffffffffu, sq, o);
            if (lane == 0) sm_red[wid] = sq;
            __syncthreads();
            if (tid == 0) {
                float tt = 0.f;
#pragma unroll
                for (int k = 0; k < NWARP; k++) tt += sm_red[k];
                sm_scale = tt / (1.0f + tt) / (sqrtf(tt) + EPS);
            }
            __syncthreads();
            const float scale = sm_scale;
#pragma unroll
            for (int r = 0; r < 2; r++) {
                int idx = tid + r * TPB;
                float v = sr[r] * scale;
                if (t == 0)      g_v[idx] = v;       // overwrite: no init launch
                else if (t == 1) g_v[idx] += v;      // cumulative for iter 2
                else             out[idx] = v;       // final output
            }
            __threadfence();
            __syncthreads();
            if (tid == 0) {
                if (t < 2) {
                    atomicExch(&g_flag[t], 1u);      // release
                } else {
                    g_cnt[0] = 0u; g_cnt[1] = 0u; g_cnt[2] = 0u;   // replay reset
                    g_flag[0] = 0u; g_flag[1] = 0u;
                }
            }
        } else {
            if (t == 2) return;                      // partials written; done
            if (tid == 0) {
                while (atomicAdd(&g_flag[t], 0u) == 0u) __nanosleep(64);
            }
            __syncthreads();
            __threadfence();
        }
    }
}

// ---------------------------------------------------------------------------
extern "C" void kernel_launch(void* const* d_in, const int* in_sizes, int n_in,
                              void* d_out, int out_size) {
    const float* x = (const float*)d_in[0];
    const float* W = (const float*)d_in[1];
    if (in_sizes[0] > in_sizes[1]) { const float* t = x; x = W; W = t; }
    float* out = (float*)d_out;

    cudaFuncSetAttribute(caps_kernel,
                         cudaFuncAttributeMaxDynamicSharedMemorySize, SMEM_U_BYTES);
    caps_kernel<<<GRID, TPB, SMEM_U_BYTES>>>(W, x, out);
}

// round 8
// speedup vs baseline: 1.3988x; 1.0423x over previous
#include <cuda_runtime.h>
#include <cuda_fp16.h>
#include <math.h>

#define N_CAPS 64
#define IN_CAPS 4096
#define CAP_DIM 32
#define IN_DIM 16
#define EPS 1e-7f

#define GRID 128                 // <= 148 SMs: all blocks co-resident (1 block/SM)
#define TPB 1024
#define NWARP 32
#define PPB (N_CAPS * IN_CAPS / GRID)   // 2048 pairs per block
#define PPW (PPB / NWARP)               // 64 pairs per warp
#define SMEM_U_BYTES (PPB * CAP_DIM * 2)  // 131072 B of fp16 u

// globals (allocation-free rule)
__device__ float g_ps[GRID][CAP_DIM];     // per-block partial S
__device__ float g_pz[GRID];              // per-block partial Z
__device__ float g_v[N_CAPS * CAP_DIM];   // cumulative v
__device__ unsigned int g_cnt[3] = {0u, 0u, 0u};
__device__ unsigned int g_flag[2] = {0u, 0u};

__global__ void __launch_bounds__(TPB, 1)
caps_kernel(const float* __restrict__ W, const float* __restrict__ x,
            float* __restrict__ out)
{
    extern __shared__ unsigned int u_sm[];   // half2 words: [pair*16 + k] = dims 2k,2k+1
    __half* const u_h = reinterpret_cast<__half*>(u_sm);
    const int tid  = threadIdx.x;
    const int wid  = tid >> 5;
    const int lane = tid & 31;
    const int blk  = blockIdx.x;
    const int n     = blk >> 1;                      // 2 blocks per output capsule
    const int ibase = (blk & 1) * (IN_CAPS / 2);

    __shared__ float2 sm_A[NWARP][CAP_DIM];
    __shared__ float  sm_z[NWARP];
    __shared__ float  sm_red[NWARP];
    __shared__ float  sm_scale;
    __shared__ unsigned int sm_last;

    // ---------------- Phase A: u = W.x, fully-coalesced W stream.
    // Pair W block = 2048B contiguous. Warp loads it as 4 coalesced LDG.128:
    // lane l takes float4 (j*32 + l) = k-chunk (l&3) of dim 8j + (l>>2).
    // 4-lane xor-reduce (offsets 1,2) completes the dots; lane keeps dim
    // (l>>2) + 8*(l&3). 32 lanes cover all 32 dims; STS.U16 layout is
    // byte-identical to what Phase B reads (half2 word k = dims 2k,2k+1).
    // L1 wavefronts/pair: ~17 vs ~65 for the strided (lane=dim) layout.
    {
        const int p0  = wid * PPW;
        const int m   = lane >> 2;           // dim sub-index
        const int kc  = lane & 3;            // k-chunk
        const int mydim = m + 8 * kc;        // dim this lane stores/accumulates
        float A0 = 0.f;

        const float4* wp = reinterpret_cast<const float4*>(
            W + (size_t)(n * IN_CAPS + ibase + p0) * (CAP_DIM * IN_DIM));
        const float4* xp = reinterpret_cast<const float4*>(
            x + (size_t)(ibase + p0) * IN_DIM);

#pragma unroll 2
        for (int p = 0; p < PPW; p++) {
            const float4* base = wp + p * 128;        // 128 float4s per pair
            float4 w0 = base[lane];
            float4 w1 = base[lane + 32];
            float4 w2 = base[lane + 64];
            float4 w3 = base[lane + 96];
            float4 xv = __ldg(xp + p * 4 + kc);       // this lane's k-chunk of x

            float d0 = w0.x * xv.x + w0.y * xv.y + w0.z * xv.z + w0.w * xv.w; // dim m
            float d1 = w1.x * xv.x + w1.y * xv.y + w1.z * xv.z + w1.w * xv.w; // dim m+8
            float d2 = w2.x * xv.x + w2.y * xv.y + w2.z * xv.z + w2.w * xv.w; // dim m+16
            float d3 = w3.x * xv.x + w3.y * xv.y + w3.z * xv.z + w3.w * xv.w; // dim m+24

            d0 += __shfl_xor_sync(0xffffffffu, d0, 1);
            d1 += __shfl_xor_sync(0xffffffffu, d1, 1);
            d2 += __shfl_xor_sync(0xffffffffu, d2, 1);
            d3 += __shfl_xor_sync(0xffffffffu, d3, 1);
            d0 += __shfl_xor_sync(0xffffffffu, d0, 2);
            d1 += __shfl_xor_sync(0xffffffffu, d1, 2);
            d2 += __shfl_xor_sync(0xffffffffu, d2, 2);
            d3 += __shfl_xor_sync(0xffffffffu, d3, 2);

            float u = (kc == 0) ? d0 : (kc == 1) ? d1 : (kc == 2) ? d2 : d3;
            A0 += u;
            u_h[(p0 + p) * CAP_DIM + mydim] = __float2half_rn(u);
        }
        sm_A[wid][mydim].x = A0;
    }
    __syncthreads();
    if (tid < CAP_DIM) {                    // block partial S (iter0: e == 1, exact fp32)
        float s = 0.f;
#pragma unroll
        for (int k = 0; k < NWARP; k++) s += sm_A[k][tid].x;
        g_ps[blk][tid] = s;
    }

    // ---------------- 3 routing iterations with software grid barrier
    for (int t = 0; t < 3; t++) {
        if (t > 0) {
            // Phase B: partials from SMEM u. lane k=lane&15 owns dims 2k,2k+1;
            // lanes 0-15 process even pair offsets, 16-31 odd offsets.
            const float2 vv = *reinterpret_cast<const float2*>(
                &g_v[n * CAP_DIM + 2 * (lane & 15)]);
            float ax = 0.f, ay = 0.f, z = 0.f;
            const int pbase = wid * PPW + ((lane >> 4) & 1);
#pragma unroll 4
            for (int s2 = 0; s2 < PPW / 2; s2++) {
                unsigned int wrd = u_sm[(pbase + 2 * s2) * 16 + (lane & 15)];
                __half2 h = *reinterpret_cast<__half2*>(&wrd);
                float2 uu = __half22float2(h);
                float dt = uu.x * vv.x + uu.y * vv.y;
                dt += __shfl_xor_sync(0xffffffffu, dt, 1);
                dt += __shfl_xor_sync(0xffffffffu, dt, 2);
                dt += __shfl_xor_sync(0xffffffffu, dt, 4);
                dt += __shfl_xor_sync(0xffffffffu, dt, 8);   // 16-lane group dot
                float e = __expf(dt);
                ax += e * uu.x; ay += e * uu.y; z += e;
            }
            sm_A[wid][lane] = make_float2(ax, ay);
#pragma unroll
            for (int o = 16; o > 0; o >>= 1) z += __shfl_xor_sync(0xffffffffu, z, o);
            if (lane == 0) sm_z[wid] = z;
            __syncthreads();
            if (tid < CAP_DIM) {
                const int k = tid >> 1, j = tid & 1;
                float s = 0.f;
#pragma unroll
                for (int w2 = 0; w2 < NWARP; w2++) {
                    float2 a = sm_A[w2][k];
                    float2 b2 = sm_A[w2][k + 16];
                    s += j ? (a.y + b2.y) : (a.x + b2.x);
                }
                g_ps[blk][tid] = s;
            } else if (tid == CAP_DIM) {
                float zt = 0.f;
#pragma unroll
                for (int w2 = 0; w2 < NWARP; w2++) zt += sm_z[w2];
                g_pz[blk] = zt * (1.f / 16.f);   // each pair's e counted 16x
            }
        }

        // ---- arrive ----
        __threadfence();
        __syncthreads();
        if (tid == 0) {
            unsigned int prev = atomicAdd(&g_cnt[t], 1u);
            sm_last = (prev == GRID - 1) ? 1u : 0u;
        }
        __syncthreads();

        if (sm_last) {
            // ---- combine (deterministic fixed-order reduction) ----
            __threadfence();
            float sr[2]; float sq = 0.f;
#pragma unroll
            for (int r = 0; r < 2; r++) {
                int idx = tid + r * TPB;        // idx = n2*32 + d  (2048 total)
                int n2 = idx >> 5, d = idx & 31;
                float num = g_ps[2 * n2][d] + g_ps[2 * n2 + 1][d];
                float Z = (t == 0) ? (float)IN_CAPS : (g_pz[2 * n2] + g_pz[2 * n2 + 1]);
                float s = num / Z;
                sr[r] = s; sq += s * s;
            }
#pragma unroll
            for (int o = 16; o > 0; o >>= 1) sq += __shfl_xor_sync(0xffffffffu, sq, o);
            if (lane == 0) sm_red[wid] = sq;
            __syncthreads();
            if (tid == 0) {
                float tt = 0.f;
#pragma unroll
                for (int k = 0; k < NWARP; k++) tt += sm_red[k];
                sm_scale = tt / (1.0f + tt) / (sqrtf(tt) + EPS);
            }
            __syncthreads();
            const float scale = sm_scale;
#pragma unroll
            for (int r = 0; r < 2; r++) {
                int idx = tid + r * TPB;
                float v = sr[r] * scale;
                if (t == 0)      g_v[idx] = v;       // overwrite: no init launch
                else if (t == 1) g_v[idx] += v;      // cumulative for iter 2
                else             out[idx] = v;       // final output
            }
            __threadfence();
            __syncthreads();
            if (tid == 0) {
                if (t < 2) {
                    atomicExch(&g_flag[t], 1u);      // release
                } else {
                    g_cnt[0] = 0u; g_cnt[1] = 0u; g_cnt[2] = 0u;   // replay reset
                    g_flag[0] = 0u; g_flag[1] = 0u;
                }
            }
        } else {
            if (t == 2) return;                      // partials written; done
            if (tid == 0) {
                while (atomicAdd(&g_flag[t], 0u) == 0u) __nanosleep(64);
            }
            __syncthreads();
            __threadfence();
        }
    }
}

// ---------------------------------------------------------------------------
extern "C" void kernel_launch(void* const* d_in, const int* in_sizes, int n_in,
                              void* d_out, int out_size) {
    const float* x = (const float*)d_in[0];
    const float* W = (const float*)d_in[1];
    if (in_sizes[0] > in_sizes[1]) { const float* t = x; x = W; W = t; }
    float* out = (float*)d_out;

    cudaFuncSetAttribute(caps_kernel,
                         cudaFuncAttributeMaxDynamicSharedMemorySize, SMEM_U_BYTES);
    caps_kernel<<<GRID, TPB, SMEM_U_BYTES>>>(W, x, out);
}